// round 8
// baseline (speedup 1.0000x reference)
#include <cuda_runtime.h>
#include <cuda_fp16.h>
#include <math_constants.h>
#include <cstdint>

// Problem constants
#define BB 8
#define TT 8192
#define DD 512
#define QQ 1024
#define CC 4096
#define MM (BB * TT)   // 65536

typedef __half h16;

// ---------------------------------------------------------------------------
// Scratch (__device__ globals; allocation-free rule)
// ---------------------------------------------------------------------------
__device__ __align__(16) h16 g_x_hi[(size_t)MM * DD];
__device__ __align__(16) h16 g_x_lo[(size_t)MM * DD];
__device__ __align__(16) h16 g_w2t_hi[(size_t)CC * DD];   // W2^T [C][D]
__device__ __align__(16) h16 g_w2t_lo[(size_t)CC * DD];
__device__ __align__(16) h16 g_ew_hi[(size_t)QQ * DD];
__device__ __align__(16) h16 g_sc[(size_t)MM * CC];       // approx scores (512 MB)
__device__ float g_csq[CC];

// ---------------------------------------------------------------------------
// PTX helpers
// ---------------------------------------------------------------------------
__device__ __forceinline__ uint32_t smem_u32(const void* p) {
    uint32_t a;
    asm("{ .reg .u64 t; cvta.to.shared.u64 t, %1; cvt.u32.u64 %0, t; }"
        : "=r"(a) : "l"(p));
    return a;
}
__device__ __forceinline__ void cp16(uint32_t dst, const void* src) {
    asm volatile("cp.async.cg.shared.global [%0], [%1], 16;" :: "r"(dst), "l"(src));
}
#define CP_COMMIT() asm volatile("cp.async.commit_group;")
#define CP_WAIT1()  asm volatile("cp.async.wait_group 1;")
#define CP_WAIT0()  asm volatile("cp.async.wait_group 0;")

__device__ __forceinline__ void ldmx4(uint32_t* r, uint32_t addr) {
    asm volatile("ldmatrix.sync.aligned.m8n8.x4.shared.b16 {%0,%1,%2,%3}, [%4];"
                 : "=r"(r[0]), "=r"(r[1]), "=r"(r[2]), "=r"(r[3]) : "r"(addr));
}
__device__ __forceinline__ void mma16816_f32(float* d, const uint32_t* a,
                                             uint32_t b0, uint32_t b1) {
    asm volatile("mma.sync.aligned.m16n8k16.row.col.f32.f16.f16.f32 "
                 "{%0,%1,%2,%3}, {%4,%5,%6,%7}, {%8,%9}, {%0,%1,%2,%3};"
                 : "+f"(d[0]), "+f"(d[1]), "+f"(d[2]), "+f"(d[3])
                 : "r"(a[0]), "r"(a[1]), "r"(a[2]), "r"(a[3]), "r"(b0), "r"(b1));
}
__device__ __forceinline__ void mma16816_f16(uint32_t* d, const uint32_t* a,
                                             uint32_t b0, uint32_t b1) {
    asm volatile("mma.sync.aligned.m16n8k16.row.col.f16.f16.f16.f16 "
                 "{%0,%1}, {%2,%3,%4,%5}, {%6,%7}, {%0,%1};"
                 : "+r"(d[0]), "+r"(d[1])
                 : "r"(a[0]), "r"(a[1]), "r"(a[2]), "r"(a[3]), "r"(b0), "r"(b1));
}

// ---------------------------------------------------------------------------
// Shared GEMM skeleton: BM=BN=128, BK=64, 256 thr, 3-stage cp.async
// ---------------------------------------------------------------------------
#define T_A    0
#define T_B    16384
#define STG1   32768
#define NSTAGE 3
#define SMEM_TOTAL (NSTAGE * STG1)

#define GEMM_PRE()                                                            \
    extern __shared__ __align__(1024) char smem[];                            \
    const uint32_t sb = smem_u32(smem);                                       \
    const int tid  = threadIdx.x;                                             \
    const int lane = tid & 31;                                                \
    const int wid  = tid >> 5;                                                \
    const int wy   = wid >> 2;                                                \
    const int wx   = wid & 3;                                                 \
    const size_t bm = (size_t)blockIdx.y * 128;                               \
    const size_t bn = (size_t)blockIdx.x * 128;                               \
    const int lrow  = tid >> 1;                                               \
    const int lhalf = tid & 1;                                                \
    const uint32_t swr   = (uint32_t)((lrow & 7) << 4);                       \
    const uint32_t rbase = (uint32_t)(lrow * 128);                            \
    const char* pA = (const char*)(A + (bm + lrow) * (size_t)K);              \
    const char* pB = (const char*)(B + (bn + lrow) * (size_t)K);              \
    const int nch = K >> 6;                                                   \
    auto load_stage = [&](int s, int kc) {                                    \
        uint32_t st = sb + (uint32_t)s * STG1;                                \
        int kbyte0 = kc << 7;                                                 \
        _Pragma("unroll")                                                     \
        for (int i = 0; i < 4; i++) {                                         \
            uint32_t ko = (uint32_t)(lhalf * 64 + i * 16);                    \
            uint32_t d  = rbase + (ko ^ swr);                                 \
            cp16(st + T_A + d, pA + kbyte0 + ko);                             \
            cp16(st + T_B + d, pB + kbyte0 + ko);                             \
        }                                                                     \
        CP_COMMIT();                                                          \
    };                                                                        \
    const int rl  = lane & 15;                                                \
    const uint32_t kbh = (uint32_t)((lane >> 4) << 4);                        \
    uint32_t a_base[4], a_swz[4], b_base[2], b_swz[2];                        \
    _Pragma("unroll")                                                         \
    for (int mf = 0; mf < 4; mf++) {                                          \
        int r = wy * 64 + mf * 16 + rl;                                       \
        a_base[mf] = (uint32_t)(r * 128);                                     \
        a_swz[mf]  = (uint32_t)((r & 7) << 4);                                \
    }                                                                         \
    _Pragma("unroll")                                                         \
    for (int np = 0; np < 2; np++) {                                          \
        int n = wx * 32 + np * 16 + rl;                                       \
        b_base[np] = (uint32_t)(n * 128);                                     \
        b_swz[np]  = (uint32_t)((n & 7) << 4);                                \
    }

#define GEMM_MAINLOOP()                                                       \
    load_stage(0, 0);                                                         \
    if (nch > 1) load_stage(1, 1);                                            \
    int sidx = 0;                                                             \
    for (int kc = 0; kc < nch; kc++) {                                        \
        if (kc + 1 < nch) { CP_WAIT1(); } else { CP_WAIT0(); }                \
        __syncthreads();                                                      \
        if (kc + 2 < nch) {                                                   \
            int s2 = sidx + 2; if (s2 >= NSTAGE) s2 -= NSTAGE;                \
            load_stage(s2, kc + 2);                                           \
        }                                                                     \
        compute_stage(sidx);                                                  \
        if (++sidx == NSTAGE) sidx = 0;                                       \
    }

// ---------------------------------------------------------------------------
// Screen GEMM: f16 accum, 1-pass hi. score = csq[c] - 2*dot.
// Epilogue stages the 128x128 fp16 score tile in smem (272B padded rows,
// conflict-free), then writes g_sc with one warp per row (256B contiguous).
// ---------------------------------------------------------------------------
#define SCPAD 272   // 128 halfs * 2B + 16B pad

__global__ __launch_bounds__(256, 2) void hgemm_screen(
    const h16* __restrict__ A, const h16* __restrict__ B, int K)
{
    GEMM_PRE();

    uint32_t acc[4][4][2];   // half2: [sub] -> rows r,r+8; cols c,c+1
    #pragma unroll
    for (int i = 0; i < 4; i++)
        #pragma unroll
        for (int j = 0; j < 4; j++) { acc[i][j][0] = 0u; acc[i][j][1] = 0u; }

    auto compute_stage = [&](int s) {
        uint32_t base = sb + (uint32_t)s * STG1;
        uint32_t aP = base + T_A, bP = base + T_B;
        #pragma unroll
        for (int ks = 0; ks < 4; ks++) {
            uint32_t kb = (uint32_t)(ks * 32) + kbh;
            uint32_t a_h[4][4], b_h[2][4];
            #pragma unroll
            for (int mf = 0; mf < 4; mf++)
                ldmx4(a_h[mf], aP + a_base[mf] + (kb ^ a_swz[mf]));
            #pragma unroll
            for (int np = 0; np < 2; np++)
                ldmx4(b_h[np], bP + b_base[np] + (kb ^ b_swz[np]));
            #pragma unroll
            for (int mf = 0; mf < 4; mf++)
                #pragma unroll
                for (int nf = 0; nf < 4; nf++) {
                    int p = nf >> 1, q = nf & 1;
                    mma16816_f16(acc[mf][nf], a_h[mf], b_h[p][q], b_h[p][q + 2]);
                }
        }
    };

    GEMM_MAINLOOP();

    // ---- epilogue: scores -> smem tile -> coalesced global ----
    __syncthreads();   // stage buffers now reusable
    const int qrow = lane >> 2;
    const int c2   = 2 * (lane & 3);
    #pragma unroll
    for (int mf = 0; mf < 4; mf++) {
        #pragma unroll
        for (int sub = 0; sub < 2; sub++) {
            int row = wy * 64 + mf * 16 + sub * 8 + qrow;
            #pragma unroll
            for (int nf = 0; nf < 4; nf++) {
                int col = wx * 32 + nf * 8 + c2;
                __half2 d2 = *(__half2*)&acc[mf][nf][sub];
                float s0 = g_csq[bn + col]     - 2.0f * __half2float(__low2half(d2));
                float s1 = g_csq[bn + col + 1] - 2.0f * __half2float(__high2half(d2));
                __half2 hp = __floats2half2_rn(s0, s1);
                *(__half2*)(smem + row * SCPAD + col * 2) = hp;
            }
        }
    }
    __syncthreads();
    // one warp per row: 256B contiguous stores
    #pragma unroll
    for (int r0 = 0; r0 < 16; r0++) {
        int row = wid * 16 + r0;
        uint2 val = *(uint2*)(smem + row * SCPAD + lane * 8);
        __stcs((uint2*)(g_sc + (bm + row) * CC + bn) + lane, val);
    }
}

// ---------------------------------------------------------------------------
// Encoder GEMM: fp32 accum, 1-pass hi. outf = A@B^T + bias.
// ---------------------------------------------------------------------------
__global__ __launch_bounds__(256, 2) void hgemm_enc(
    const h16* __restrict__ A, const h16* __restrict__ B,
    int K, int Ntot, const float* __restrict__ bias, float* __restrict__ outf)
{
    GEMM_PRE();

    float acc[4][4][4];
    #pragma unroll
    for (int i = 0; i < 4; i++)
        #pragma unroll
        for (int j = 0; j < 4; j++)
            #pragma unroll
            for (int k = 0; k < 4; k++) acc[i][j][k] = 0.f;

    auto compute_stage = [&](int s) {
        uint32_t base = sb + (uint32_t)s * STG1;
        uint32_t aP = base + T_A, bP = base + T_B;
        #pragma unroll
        for (int ks = 0; ks < 4; ks++) {
            uint32_t kb = (uint32_t)(ks * 32) + kbh;
            uint32_t a_h[4][4], b_h[2][4];
            #pragma unroll
            for (int mf = 0; mf < 4; mf++)
                ldmx4(a_h[mf], aP + a_base[mf] + (kb ^ a_swz[mf]));
            #pragma unroll
            for (int np = 0; np < 2; np++)
                ldmx4(b_h[np], bP + b_base[np] + (kb ^ b_swz[np]));
            #pragma unroll
            for (int mf = 0; mf < 4; mf++)
                #pragma unroll
                for (int nf = 0; nf < 4; nf++) {
                    int p = nf >> 1, q = nf & 1;
                    mma16816_f32(acc[mf][nf], a_h[mf], b_h[p][q], b_h[p][q + 2]);
                }
        }
    };

    GEMM_MAINLOOP();

    const int qrow = lane >> 2;
    const int c2   = 2 * (lane & 3);
    #pragma unroll
    for (int mf = 0; mf < 4; mf++) {
        size_t r0 = bm + (size_t)(wy * 64 + mf * 16 + qrow);
        #pragma unroll
        for (int nf = 0; nf < 4; nf++) {
            size_t col = bn + (size_t)(wx * 32 + nf * 8 + c2);
            float b0 = bias[col], b1 = bias[col + 1];
            #pragma unroll
            for (int sub = 0; sub < 2; sub++) {
                size_t r = r0 + sub * 8;
                float2 o;
                o.x = acc[mf][nf][sub * 2 + 0] + b0;
                o.y = acc[mf][nf][sub * 2 + 1] + b1;
                *(float2*)(outf + r * Ntot + col) = o;
            }
        }
    }
}

// ---------------------------------------------------------------------------
// Refine: one warp per row. Loads all 4096 fp16 scores into registers,
// computes the row min itself (no atomics), then exact fp32 recompute of
// candidates within MARGIN. Tie-break: lowest index.
// MARGIN covers dropped-lo (~0.6), f16-accum rounding (~1.0), store ulp 0.5.
// ---------------------------------------------------------------------------
#define MARGIN 8.0f

__global__ __launch_bounds__(256) void refine_kernel(float* __restrict__ labels) {
    int warp = blockIdx.x * 8 + (threadIdx.x >> 5);
    int lane = threadIdx.x & 31;
    size_t row = (size_t)warp;

    const h16* sr = g_sc + row * CC;
    uint4 v[16];                         // 16 * 8 halfs = 128 scores per lane
    #pragma unroll
    for (int i = 0; i < 16; i++)
        v[i] = *(const uint4*)(sr + i * 256 + lane * 8);

    // row min from registers
    __half2 m2 = *(__half2*)&v[0].x;
    #pragma unroll
    for (int i = 0; i < 16; i++) {
        const __half2* p = (const __half2*)&v[i];
        m2 = __hmin2(m2, __hmin2(__hmin2(p[0], p[1]), __hmin2(p[2], p[3])));
    }
    float lmin = fminf(__half2float(__low2half(m2)), __half2float(__high2half(m2)));
    #pragma unroll
    for (int off = 16; off > 0; off >>= 1)
        lmin = fminf(lmin, __shfl_xor_sync(0xFFFFFFFFu, lmin, off));
    const float thresh = lmin + MARGIN;

    float best = CUDART_INF_F;
    int bestc = 0;

    #pragma unroll
    for (int i = 0; i < 16; i++) {
        const __half2* p = (const __half2*)&v[i];
        __half2 mm2 = __hmin2(__hmin2(p[0], p[1]), __hmin2(p[2], p[3]));
        float mlo = fminf(__half2float(__low2half(mm2)),
                          __half2float(__high2half(mm2)));
        uint32_t mask = __ballot_sync(0xFFFFFFFFu, mlo <= thresh);
        while (mask) {
            int bit = __ffs(mask) - 1;
            mask &= mask - 1;
            uint4 w;
            w.x = __shfl_sync(0xFFFFFFFFu, v[i].x, bit);
            w.y = __shfl_sync(0xFFFFFFFFu, v[i].y, bit);
            w.z = __shfl_sync(0xFFFFFFFFu, v[i].z, bit);
            w.w = __shfl_sync(0xFFFFFFFFu, v[i].w, bit);
            const __half* hh = (const __half*)&w;
            #pragma unroll
            for (int j = 0; j < 8; j++) {
                float sv = __half2float(hh[j]);
                if (sv > thresh) continue;
                int c = i * 256 + bit * 8 + j;
                const h16* xh = g_x_hi + row * DD;
                const h16* xl = g_x_lo + row * DD;
                const h16* wh = g_w2t_hi + (size_t)c * DD;
                const h16* wl = g_w2t_lo + (size_t)c * DD;
                float dot = 0.f;
                #pragma unroll
                for (int jj = 0; jj < 16; jj++) {
                    int d = lane + 32 * jj;
                    float a = __half2float(xh[d]) + __half2float(xl[d]);
                    float b = __half2float(wh[d]) + __half2float(wl[d]);
                    dot = fmaf(a, b, dot);
                }
                #pragma unroll
                for (int off = 16; off > 0; off >>= 1)
                    dot += __shfl_down_sync(0xFFFFFFFFu, dot, off);
                if (lane == 0) {
                    float sc = g_csq[c] - 2.0f * dot;
                    if (sc < best || (sc == best && c < bestc)) { best = sc; bestc = c; }
                }
            }
        }
    }
    if (lane == 0) labels[row] = (float)bestc;
}

// ---------------------------------------------------------------------------
// W2^T precompute: W2T[c][d] = sum_q cb[q][c]*projw[q][d], fp32, split fp16.
// ---------------------------------------------------------------------------
__global__ __launch_bounds__(256) void w2t_kernel(const float* __restrict__ projw,
                                                  const float* __restrict__ cb) {
    __shared__ __align__(16) float As[8][128];
    __shared__ __align__(16) float Bs[8][128];

    int tid = threadIdx.x;
    int c0 = blockIdx.x * 128;
    int d0 = blockIdx.y * 128;
    int lr = tid >> 5, lc = (tid & 31) * 4;
    int ty = tid >> 4, tx = tid & 15;

    float acc[8][8];
    #pragma unroll
    for (int i = 0; i < 8; i++)
        #pragma unroll
        for (int j = 0; j < 8; j++) acc[i][j] = 0.f;

    for (int k0 = 0; k0 < QQ; k0 += 8) {
        *(float4*)&As[lr][lc] = *(const float4*)(cb + (size_t)(k0 + lr) * CC + c0 + lc);
        *(float4*)&Bs[lr][lc] = *(const float4*)(projw + (size_t)(k0 + lr) * DD + d0 + lc);
        __syncthreads();
        #pragma unroll
        for (int k = 0; k < 8; k++) {
            float ar[8], br[8];
            float4 a0 = *(const float4*)&As[k][ty * 8];
            float4 a1 = *(const float4*)&As[k][ty * 8 + 4];
            float4 b0 = *(const float4*)&Bs[k][tx * 8];
            float4 b1 = *(const float4*)&Bs[k][tx * 8 + 4];
            ar[0]=a0.x; ar[1]=a0.y; ar[2]=a0.z; ar[3]=a0.w;
            ar[4]=a1.x; ar[5]=a1.y; ar[6]=a1.z; ar[7]=a1.w;
            br[0]=b0.x; br[1]=b0.y; br[2]=b0.z; br[3]=b0.w;
            br[4]=b1.x; br[5]=b1.y; br[6]=b1.z; br[7]=b1.w;
            #pragma unroll
            for (int i = 0; i < 8; i++)
                #pragma unroll
                for (int j = 0; j < 8; j++)
                    acc[i][j] = fmaf(ar[i], br[j], acc[i][j]);
        }
        __syncthreads();
    }

    #pragma unroll
    for (int i = 0; i < 8; i++) {
        size_t rowo = (size_t)(c0 + ty * 8 + i) * DD + d0 + tx * 8;
        #pragma unroll
        for (int j = 0; j < 8; j++) {
            float v = acc[i][j];
            h16 h = __float2half(v);
            g_w2t_hi[rowo + j] = h;
            g_w2t_lo[rowo + j] = __float2half(v - __half2float(h));
        }
    }
}

// ---------------------------------------------------------------------------
// LayerNorm over D=512, writes fp16 hi/lo split.
// ---------------------------------------------------------------------------
__global__ __launch_bounds__(256) void ln_kernel(const float* __restrict__ x,
                                                 const float* __restrict__ gamma,
                                                 const float* __restrict__ beta) {
    int r = blockIdx.x;
    const float* xr = x + (size_t)r * DD;
    int t = threadIdx.x;

    float v0 = xr[t], v1 = xr[t + 256];
    float s = v0 + v1, ss = v0 * v0 + v1 * v1;
    #pragma unroll
    for (int off = 16; off > 0; off >>= 1) {
        s  += __shfl_down_sync(0xFFFFFFFFu, s,  off);
        ss += __shfl_down_sync(0xFFFFFFFFu, ss, off);
    }
    __shared__ float sh_s[8], sh_ss[8];
    int w = t >> 5, l = t & 31;
    if (l == 0) { sh_s[w] = s; sh_ss[w] = ss; }
    __syncthreads();
    if (t == 0) {
        float S = 0.f, SS = 0.f;
        #pragma unroll
        for (int i = 0; i < 8; i++) { S += sh_s[i]; SS += sh_ss[i]; }
        sh_s[0]  = S * (1.0f / DD);
        sh_ss[0] = SS * (1.0f / DD);
    }
    __syncthreads();
    float mu = sh_s[0];
    float rs = rsqrtf(sh_ss[0] - mu * mu + 1e-5f);

    float y0 = (v0 - mu) * rs * gamma[t]       + beta[t];
    float y1 = (v1 - mu) * rs * gamma[t + 256] + beta[t + 256];

    size_t base = (size_t)r * DD;
    h16 h0 = __float2half(y0), h1 = __float2half(y1);
    g_x_hi[base + t]       = h0;
    g_x_hi[base + t + 256] = h1;
    g_x_lo[base + t]       = __float2half(y0 - __half2float(h0));
    g_x_lo[base + t + 256] = __float2half(y1 - __half2float(h1));
}

// ---------------------------------------------------------------------------
__global__ __launch_bounds__(256) void split_hi_kernel(const float* __restrict__ src,
                                                       h16* __restrict__ hi, int n) {
    int i = blockIdx.x * 256 + threadIdx.x;
    if (i < n) hi[i] = __float2half(src[i]);
}

// csq, atomic-free: block b handles 64 c's; 4 q-groups of 256 per c.
__global__ __launch_bounds__(256) void csq_kernel(const float* __restrict__ cb) {
    __shared__ float red[4][64];
    int t = threadIdx.x;
    int tq = t >> 6;          // 0..3
    int tc = t & 63;          // 0..63
    int c = blockIdx.x * 64 + tc;
    float s = 0.f;
    #pragma unroll 4
    for (int q = tq * 256; q < tq * 256 + 256; q++) {
        float v = cb[(size_t)q * CC + c];
        s += v * v;
    }
    red[tq][tc] = s;
    __syncthreads();
    if (t < 64)
        g_csq[blockIdx.x * 64 + t] = red[0][t] + red[1][t] + red[2][t] + red[3][t];
}

// ---------------------------------------------------------------------------
extern "C" void kernel_launch(void* const* d_in, const int* in_sizes, int n_in,
                              void* d_out, int out_size) {
    const float* x     = (const float*)d_in[0];
    const float* gamma = (const float*)d_in[1];
    const float* beta  = (const float*)d_in[2];
    const float* projw = (const float*)d_in[3];
    const float* cb    = (const float*)d_in[4];
    const float* encw  = (const float*)d_in[5];
    const float* encb  = (const float*)d_in[6];

    float* out     = (float*)d_out;
    float* enc_out = out;                               // (M, Q) fp32
    float* labels  = out + ((size_t)out_size - MM);     // (M,) as fp32

    h16 *xh, *w2h, *ewh;
    cudaGetSymbolAddress((void**)&xh, g_x_hi);
    cudaGetSymbolAddress((void**)&w2h, g_w2t_hi);
    cudaGetSymbolAddress((void**)&ewh, g_ew_hi);

    cudaFuncSetAttribute(hgemm_enc, cudaFuncAttributeMaxDynamicSharedMemorySize,
                         SMEM_TOTAL);
    cudaFuncSetAttribute(hgemm_screen, cudaFuncAttributeMaxDynamicSharedMemorySize,
                         SMEM_TOTAL);

    // Order chosen so the ncu capture slot (4th launch) lands on hgemm_screen.
    // 1) LayerNorm -> fp16 split
    ln_kernel<<<MM, 256>>>(x, gamma, beta);

    // 2) fused codebook matrix W2^T + csq
    w2t_kernel<<<dim3(CC / 128, DD / 128), 256>>>(projw, cb);
    csq_kernel<<<CC / 64, 256>>>(cb);

    // 3) label screen (f16-accum 1-pass): coalesced score store
    dim3 gridx(CC / 128, MM / 128);
    hgemm_screen<<<gridx, 256, SMEM_TOTAL>>>(xh, w2h, DD);

    // 4) enc weight split + encoder GEMM (fp32-accum 1-pass)
    split_hi_kernel<<<(QQ * DD + 255) / 256, 256>>>(encw, ewh, QQ * DD);
    dim3 grid12(QQ / 128, MM / 128);
    hgemm_enc<<<grid12, 256, SMEM_TOTAL>>>(xh, ewh, DD, QQ, encb, enc_out);

    // 5) refine (computes row min itself; no atomics) -> labels
    refine_kernel<<<MM / 8, 256>>>(labels);

    (void)in_sizes; (void)n_in;
}

// round 10
// speedup vs baseline: 1.3631x; 1.3631x over previous
#include <cuda_runtime.h>
#include <cuda_fp16.h>
#include <math_constants.h>
#include <cstdint>

// Problem constants
#define BB 8
#define TT 8192
#define DD 512
#define QQ 1024
#define CC 4096
#define MM (BB * TT)   // 65536

typedef __half h16;

// ---------------------------------------------------------------------------
// Scratch (__device__ globals; allocation-free rule)
// ---------------------------------------------------------------------------
__device__ __align__(16) h16 g_x_hi[(size_t)MM * DD];
__device__ __align__(16) h16 g_x_lo[(size_t)MM * DD];
__device__ __align__(16) h16 g_w2t_hi[(size_t)CC * DD];   // W2^T [C][D]
__device__ __align__(16) h16 g_w2t_lo[(size_t)CC * DD];
__device__ __align__(16) h16 g_ew_hi[(size_t)QQ * DD];
__device__ __align__(16) h16 g_sc[(size_t)MM * CC];       // approx scores (512 MB)
__device__ float g_csq[CC];
__device__ unsigned long long g_key[MM];

// ---------------------------------------------------------------------------
// PTX helpers
// ---------------------------------------------------------------------------
__device__ __forceinline__ uint32_t smem_u32(const void* p) {
    uint32_t a;
    asm("{ .reg .u64 t; cvta.to.shared.u64 t, %1; cvt.u32.u64 %0, t; }"
        : "=r"(a) : "l"(p));
    return a;
}
__device__ __forceinline__ void cp16(uint32_t dst, const void* src) {
    asm volatile("cp.async.cg.shared.global [%0], [%1], 16;" :: "r"(dst), "l"(src));
}
#define CP_COMMIT() asm volatile("cp.async.commit_group;")
#define CP_WAIT1()  asm volatile("cp.async.wait_group 1;")
#define CP_WAIT0()  asm volatile("cp.async.wait_group 0;")

__device__ __forceinline__ void ldmx4(uint32_t* r, uint32_t addr) {
    asm volatile("ldmatrix.sync.aligned.m8n8.x4.shared.b16 {%0,%1,%2,%3}, [%4];"
                 : "=r"(r[0]), "=r"(r[1]), "=r"(r[2]), "=r"(r[3]) : "r"(addr));
}
__device__ __forceinline__ void mma16816_f32(float* d, const uint32_t* a,
                                             uint32_t b0, uint32_t b1) {
    asm volatile("mma.sync.aligned.m16n8k16.row.col.f32.f16.f16.f32 "
                 "{%0,%1,%2,%3}, {%4,%5,%6,%7}, {%8,%9}, {%0,%1,%2,%3};"
                 : "+f"(d[0]), "+f"(d[1]), "+f"(d[2]), "+f"(d[3])
                 : "r"(a[0]), "r"(a[1]), "r"(a[2]), "r"(a[3]), "r"(b0), "r"(b1));
}
__device__ __forceinline__ void mma16816_f16(uint32_t* d, const uint32_t* a,
                                             uint32_t b0, uint32_t b1) {
    asm volatile("mma.sync.aligned.m16n8k16.row.col.f16.f16.f16.f16 "
                 "{%0,%1}, {%2,%3,%4,%5}, {%6,%7}, {%0,%1};"
                 : "+r"(d[0]), "+r"(d[1])
                 : "r"(a[0]), "r"(a[1]), "r"(a[2]), "r"(a[3]), "r"(b0), "r"(b1));
}

// float <-> order-preserving uint32 (ascending)
__device__ __forceinline__ uint32_t ford(float s) {
    uint32_t b = __float_as_uint(s);
    return (b & 0x80000000u) ? ~b : (b | 0x80000000u);
}
__device__ __forceinline__ float unford(uint32_t f) {
    uint32_t b = (f & 0x80000000u) ? (f & 0x7FFFFFFFu) : ~f;
    return __uint_as_float(b);
}

// ---------------------------------------------------------------------------
// Shared GEMM skeleton: BM=BN=128, BK=64, 256 thr, 3-stage cp.async
// ---------------------------------------------------------------------------
#define T_A    0
#define T_B    16384
#define STG1   32768
#define NSTAGE 3
#define SMEM_TOTAL (NSTAGE * STG1)

#define GEMM_PRE()                                                            \
    extern __shared__ __align__(1024) char smem[];                            \
    const uint32_t sb = smem_u32(smem);                                       \
    const int tid  = threadIdx.x;                                             \
    const int lane = tid & 31;                                                \
    const int wid  = tid >> 5;                                                \
    const int wy   = wid >> 2;                                                \
    const int wx   = wid & 3;                                                 \
    const size_t bm = (size_t)blockIdx.y * 128;                               \
    const size_t bn = (size_t)blockIdx.x * 128;                               \
    const int lrow  = tid >> 1;                                               \
    const int lhalf = tid & 1;                                                \
    const uint32_t swr   = (uint32_t)((lrow & 7) << 4);                       \
    const uint32_t rbase = (uint32_t)(lrow * 128);                            \
    const char* pA = (const char*)(A + (bm + lrow) * (size_t)K);              \
    const char* pB = (const char*)(B + (bn + lrow) * (size_t)K);              \
    const int nch = K >> 6;                                                   \
    auto load_stage = [&](int s, int kc) {                                    \
        uint32_t st = sb + (uint32_t)s * STG1;                                \
        int kbyte0 = kc << 7;                                                 \
        _Pragma("unroll")                                                     \
        for (int i = 0; i < 4; i++) {                                         \
            uint32_t ko = (uint32_t)(lhalf * 64 + i * 16);                    \
            uint32_t d  = rbase + (ko ^ swr);                                 \
            cp16(st + T_A + d, pA + kbyte0 + ko);                             \
            cp16(st + T_B + d, pB + kbyte0 + ko);                             \
        }                                                                     \
        CP_COMMIT();                                                          \
    };                                                                        \
    const int rl  = lane & 15;                                                \
    const uint32_t kbh = (uint32_t)((lane >> 4) << 4);                        \
    uint32_t a_base[4], a_swz[4], b_base[2], b_swz[2];                        \
    _Pragma("unroll")                                                         \
    for (int mf = 0; mf < 4; mf++) {                                          \
        int r = wy * 64 + mf * 16 + rl;                                       \
        a_base[mf] = (uint32_t)(r * 128);                                     \
        a_swz[mf]  = (uint32_t)((r & 7) << 4);                                \
    }                                                                         \
    _Pragma("unroll")                                                         \
    for (int np = 0; np < 2; np++) {                                          \
        int n = wx * 32 + np * 16 + rl;                                       \
        b_base[np] = (uint32_t)(n * 128);                                     \
        b_swz[np]  = (uint32_t)((n & 7) << 4);                                \
    }

#define GEMM_MAINLOOP()                                                       \
    load_stage(0, 0);                                                         \
    if (nch > 1) load_stage(1, 1);                                            \
    int sidx = 0;                                                             \
    for (int kc = 0; kc < nch; kc++) {                                        \
        if (kc + 1 < nch) { CP_WAIT1(); } else { CP_WAIT0(); }                \
        __syncthreads();                                                      \
        if (kc + 2 < nch) {                                                   \
            int s2 = sidx + 2; if (s2 >= NSTAGE) s2 -= NSTAGE;                \
            load_stage(s2, kc + 2);                                           \
        }                                                                     \
        compute_stage(sidx);                                                  \
        if (++sidx == NSTAGE) sidx = 0;                                       \
    }

// ---------------------------------------------------------------------------
// Screen GEMM (R7-proven): f16 accum, 1-pass hi.
// score = csq[c] - 2*dot; direct fp16 score store + per-row packed atomicMin.
// ---------------------------------------------------------------------------
__global__ __launch_bounds__(256, 2) void hgemm_screen(
    const h16* __restrict__ A, const h16* __restrict__ B, int K)
{
    GEMM_PRE();

    uint32_t acc[4][4][2];   // half2 pairs: [sub] -> rows r, r+8; cols c,c+1
    #pragma unroll
    for (int i = 0; i < 4; i++)
        #pragma unroll
        for (int j = 0; j < 4; j++) { acc[i][j][0] = 0u; acc[i][j][1] = 0u; }

    auto compute_stage = [&](int s) {
        uint32_t base = sb + (uint32_t)s * STG1;
        uint32_t aP = base + T_A, bP = base + T_B;
        #pragma unroll
        for (int ks = 0; ks < 4; ks++) {
            uint32_t kb = (uint32_t)(ks * 32) + kbh;
            uint32_t a_h[4][4], b_h[2][4];
            #pragma unroll
            for (int mf = 0; mf < 4; mf++)
                ldmx4(a_h[mf], aP + a_base[mf] + (kb ^ a_swz[mf]));
            #pragma unroll
            for (int np = 0; np < 2; np++)
                ldmx4(b_h[np], bP + b_base[np] + (kb ^ b_swz[np]));
            #pragma unroll
            for (int mf = 0; mf < 4; mf++)
                #pragma unroll
                for (int nf = 0; nf < 4; nf++) {
                    int p = nf >> 1, q = nf & 1;
                    mma16816_f16(acc[mf][nf], a_h[mf], b_h[p][q], b_h[p][q + 2]);
                }
        }
    };

    GEMM_MAINLOOP();

    const int qrow = lane >> 2;
    const int c2   = 2 * (lane & 3);
    #pragma unroll
    for (int mf = 0; mf < 4; mf++) {
        #pragma unroll
        for (int sub = 0; sub < 2; sub++) {
            size_t row = bm + (size_t)(wy * 64 + mf * 16 + sub * 8 + qrow);
            unsigned long long best = 0xFFFFFFFFFFFFFFFFull;
            #pragma unroll
            for (int nf = 0; nf < 4; nf++) {
                int col = (int)bn + wx * 32 + nf * 8 + c2;
                __half2 d2 = *(__half2*)&acc[mf][nf][sub];
                float s0 = g_csq[col]     - 2.0f * __half2float(__low2half(d2));
                float s1 = g_csq[col + 1] - 2.0f * __half2float(__high2half(d2));
                __half2 hp = __floats2half2_rn(s0, s1);
                uint32_t u; *(__half2*)&u = hp;
                __stcs((uint32_t*)(g_sc + row * CC + col), u);
                unsigned long long k0 =
                    ((unsigned long long)ford(s0) << 32) | (uint32_t)col;
                unsigned long long k1 =
                    ((unsigned long long)ford(s1) << 32) | (uint32_t)(col + 1);
                if (k0 < best) best = k0;
                if (k1 < best) best = k1;
            }
            unsigned long long o;
            o = __shfl_down_sync(0xFFFFFFFFu, best, 2);
            if (o < best) best = o;
            o = __shfl_down_sync(0xFFFFFFFFu, best, 1);
            if (o < best) best = o;
            if ((lane & 3) == 0) atomicMin(&g_key[row], best);
        }
    }
}

// ---------------------------------------------------------------------------
// Encoder GEMM: fp32 accum, 1-pass hi. outf = A@B^T + bias.
// ---------------------------------------------------------------------------
__global__ __launch_bounds__(256, 2) void hgemm_enc(
    const h16* __restrict__ A, const h16* __restrict__ B,
    int K, int Ntot, const float* __restrict__ bias, float* __restrict__ outf)
{
    GEMM_PRE();

    float acc[4][4][4];
    #pragma unroll
    for (int i = 0; i < 4; i++)
        #pragma unroll
        for (int j = 0; j < 4; j++)
            #pragma unroll
            for (int k = 0; k < 4; k++) acc[i][j][k] = 0.f;

    auto compute_stage = [&](int s) {
        uint32_t base = sb + (uint32_t)s * STG1;
        uint32_t aP = base + T_A, bP = base + T_B;
        #pragma unroll
        for (int ks = 0; ks < 4; ks++) {
            uint32_t kb = (uint32_t)(ks * 32) + kbh;
            uint32_t a_h[4][4], b_h[2][4];
            #pragma unroll
            for (int mf = 0; mf < 4; mf++)
                ldmx4(a_h[mf], aP + a_base[mf] + (kb ^ a_swz[mf]));
            #pragma unroll
            for (int np = 0; np < 2; np++)
                ldmx4(b_h[np], bP + b_base[np] + (kb ^ b_swz[np]));
            #pragma unroll
            for (int mf = 0; mf < 4; mf++)
                #pragma unroll
                for (int nf = 0; nf < 4; nf++) {
                    int p = nf >> 1, q = nf & 1;
                    mma16816_f32(acc[mf][nf], a_h[mf], b_h[p][q], b_h[p][q + 2]);
                }
        }
    };

    GEMM_MAINLOOP();

    const int qrow = lane >> 2;
    const int c2   = 2 * (lane & 3);
    #pragma unroll
    for (int mf = 0; mf < 4; mf++) {
        size_t r0 = bm + (size_t)(wy * 64 + mf * 16 + qrow);
        #pragma unroll
        for (int nf = 0; nf < 4; nf++) {
            size_t col = bn + (size_t)(wx * 32 + nf * 8 + c2);
            float b0 = bias[col], b1 = bias[col + 1];
            #pragma unroll
            for (int sub = 0; sub < 2; sub++) {
                size_t r = r0 + sub * 8;
                float2 o;
                o.x = acc[mf][nf][sub * 2 + 0] + b0;
                o.y = acc[mf][nf][sub * 2 + 1] + b1;
                *(float2*)(outf + r * Ntot + col) = o;
            }
        }
    }
}

// ---------------------------------------------------------------------------
// Refine (R7-proven): streaming uint4 scan; candidates within MARGIN of the
// screen's approx min; exact fp32 recompute; low-index tie break.
// ---------------------------------------------------------------------------
#define MARGIN 8.0f

__global__ __launch_bounds__(256) void refine_kernel(float* __restrict__ labels) {
    int warp = blockIdx.x * 8 + (threadIdx.x >> 5);
    int lane = threadIdx.x & 31;
    size_t row = (size_t)warp;

    float amin   = unford((uint32_t)(g_key[row] >> 32));
    float thresh = amin + MARGIN;
    __half hthr  = __float2half_ru(thresh);

    const h16* sr = g_sc + row * CC;
    float best = CUDART_INF_F;
    int bestc = 0;

    for (int base = 0; base < CC; base += 256) {
        uint4 v = *(const uint4*)(sr + base + lane * 8);
        __half2 p[4];
        p[0] = *(__half2*)&v.x; p[1] = *(__half2*)&v.y;
        p[2] = *(__half2*)&v.z; p[3] = *(__half2*)&v.w;
        __half2 mn2 = __hmin2(__hmin2(p[0], p[1]), __hmin2(p[2], p[3]));
        __half mn = __hmin(__low2half(mn2), __high2half(mn2));
        uint32_t mask = __ballot_sync(0xFFFFFFFFu, __hle(mn, hthr));
        while (mask) {
            int bit = __ffs(mask) - 1;
            mask &= mask - 1;
            #pragma unroll
            for (int j = 0; j < 8; j++) {
                float sv = __half2float(__shfl_sync(0xFFFFFFFFu,
                             ((const __half*)p)[j], bit));
                if (sv > thresh) continue;
                int c = base + bit * 8 + j;
                const h16* xh = g_x_hi + row * DD;
                const h16* xl = g_x_lo + row * DD;
                const h16* wh = g_w2t_hi + (size_t)c * DD;
                const h16* wl = g_w2t_lo + (size_t)c * DD;
                float dot = 0.f;
                #pragma unroll
                for (int jj = 0; jj < 16; jj++) {
                    int d = lane + 32 * jj;
                    float a = __half2float(xh[d]) + __half2float(xl[d]);
                    float b = __half2float(wh[d]) + __half2float(wl[d]);
                    dot = fmaf(a, b, dot);
                }
                #pragma unroll
                for (int off = 16; off > 0; off >>= 1)
                    dot += __shfl_down_sync(0xFFFFFFFFu, dot, off);
                if (lane == 0) {
                    float sc = g_csq[c] - 2.0f * dot;
                    if (sc < best || (sc == best && c < bestc)) { best = sc; bestc = c; }
                }
            }
        }
    }
    if (lane == 0) labels[row] = (float)bestc;
}

// ---------------------------------------------------------------------------
// W2^T precompute + fused csq: W2T[c][d] = sum_q cb[q][c]*projw[q][d].
// Blocks with d0==0 also accumulate csq[c] = sum_q cb[q][c]^2 from the As
// tiles they already load.
// ---------------------------------------------------------------------------
__global__ __launch_bounds__(256) void w2t_kernel(const float* __restrict__ projw,
                                                  const float* __restrict__ cb) {
    __shared__ __align__(16) float As[8][128];
    __shared__ __align__(16) float Bs[8][128];
    __shared__ float cred[2][128];

    int tid = threadIdx.x;
    int c0 = blockIdx.x * 128;
    int d0 = blockIdx.y * 128;
    int lr = tid >> 5, lc = (tid & 31) * 4;
    int ty = tid >> 4, tx = tid & 15;

    // csq accumulation mapping (only d0==0 blocks use it)
    int qcol = tid & 127;       // column 0..127
    int qgrp = tid >> 7;        // 0..1 -> rows qgrp*4 .. +3
    float csum = 0.f;

    float acc[8][8];
    #pragma unroll
    for (int i = 0; i < 8; i++)
        #pragma unroll
        for (int j = 0; j < 8; j++) acc[i][j] = 0.f;

    for (int k0 = 0; k0 < QQ; k0 += 8) {
        *(float4*)&As[lr][lc] = *(const float4*)(cb + (size_t)(k0 + lr) * CC + c0 + lc);
        *(float4*)&Bs[lr][lc] = *(const float4*)(projw + (size_t)(k0 + lr) * DD + d0 + lc);
        __syncthreads();

        if (d0 == 0) {
            #pragma unroll
            for (int r = 0; r < 4; r++) {
                float v = As[qgrp * 4 + r][qcol];
                csum = fmaf(v, v, csum);
            }
        }

        #pragma unroll
        for (int k = 0; k < 8; k++) {
            float ar[8], br[8];
            float4 a0 = *(const float4*)&As[k][ty * 8];
            float4 a1 = *(const float4*)&As[k][ty * 8 + 4];
            float4 b0 = *(const float4*)&Bs[k][tx * 8];
            float4 b1 = *(const float4*)&Bs[k][tx * 8 + 4];
            ar[0]=a0.x; ar[1]=a0.y; ar[2]=a0.z; ar[3]=a0.w;
            ar[4]=a1.x; ar[5]=a1.y; ar[6]=a1.z; ar[7]=a1.w;
            br[0]=b0.x; br[1]=b0.y; br[2]=b0.z; br[3]=b0.w;
            br[4]=b1.x; br[5]=b1.y; br[6]=b1.z; br[7]=b1.w;
            #pragma unroll
            for (int i = 0; i < 8; i++)
                #pragma unroll
                for (int j = 0; j < 8; j++)
                    acc[i][j] = fmaf(ar[i], br[j], acc[i][j]);
        }
        __syncthreads();
    }

    if (d0 == 0) {
        cred[qgrp][qcol] = csum;
        __syncthreads();
        if (tid < 128) g_csq[c0 + tid] = cred[0][tid] + cred[1][tid];
    }

    #pragma unroll
    for (int i = 0; i < 8; i++) {
        size_t rowo = (size_t)(c0 + ty * 8 + i) * DD + d0 + tx * 8;
        #pragma unroll
        for (int j = 0; j < 8; j++) {
            float v = acc[i][j];
            h16 h = __float2half(v);
            g_w2t_hi[rowo + j] = h;
            g_w2t_lo[rowo + j] = __float2half(v - __half2float(h));
        }
    }
}

// ---------------------------------------------------------------------------
// LayerNorm over D=512, writes fp16 hi/lo split + inits g_key for its row.
// ---------------------------------------------------------------------------
__global__ __launch_bounds__(256) void ln_kernel(const float* __restrict__ x,
                                                 const float* __restrict__ gamma,
                                                 const float* __restrict__ beta) {
    int r = blockIdx.x;
    const float* xr = x + (size_t)r * DD;
    int t = threadIdx.x;

    if (t == 0) g_key[r] = 0xFFFFFFFFFFFFFFFFull;

    float v0 = xr[t], v1 = xr[t + 256];
    float s = v0 + v1, ss = v0 * v0 + v1 * v1;
    #pragma unroll
    for (int off = 16; off > 0; off >>= 1) {
        s  += __shfl_down_sync(0xFFFFFFFFu, s,  off);
        ss += __shfl_down_sync(0xFFFFFFFFu, ss, off);
    }
    __shared__ float sh_s[8], sh_ss[8];
    int w = t >> 5, l = t & 31;
    if (l == 0) { sh_s[w] = s; sh_ss[w] = ss; }
    __syncthreads();
    if (t == 0) {
        float S = 0.f, SS = 0.f;
        #pragma unroll
        for (int i = 0; i < 8; i++) { S += sh_s[i]; SS += sh_ss[i]; }
        sh_s[0]  = S * (1.0f / DD);
        sh_ss[0] = SS * (1.0f / DD);
    }
    __syncthreads();
    float mu = sh_s[0];
    float rs = rsqrtf(sh_ss[0] - mu * mu + 1e-5f);

    float y0 = (v0 - mu) * rs * gamma[t]       + beta[t];
    float y1 = (v1 - mu) * rs * gamma[t + 256] + beta[t + 256];

    size_t base = (size_t)r * DD;
    h16 h0 = __float2half(y0), h1 = __float2half(y1);
    g_x_hi[base + t]       = h0;
    g_x_hi[base + t + 256] = h1;
    g_x_lo[base + t]       = __float2half(y0 - __half2float(h0));
    g_x_lo[base + t + 256] = __float2half(y1 - __half2float(h1));
}

// ---------------------------------------------------------------------------
__global__ __launch_bounds__(256) void split_hi_kernel(const float* __restrict__ src,
                                                       h16* __restrict__ hi, int n) {
    int i = blockIdx.x * 256 + threadIdx.x;
    if (i < n) hi[i] = __float2half(src[i]);
}

// ---------------------------------------------------------------------------
extern "C" void kernel_launch(void* const* d_in, const int* in_sizes, int n_in,
                              void* d_out, int out_size) {
    const float* x     = (const float*)d_in[0];
    const float* gamma = (const float*)d_in[1];
    const float* beta  = (const float*)d_in[2];
    const float* projw = (const float*)d_in[3];
    const float* cb    = (const float*)d_in[4];
    const float* encw  = (const float*)d_in[5];
    const float* encb  = (const float*)d_in[6];

    float* out     = (float*)d_out;
    float* enc_out = out;                               // (M, Q) fp32
    float* labels  = out + ((size_t)out_size - MM);     // (M,) as fp32

    h16 *xh, *w2h, *ewh;
    cudaGetSymbolAddress((void**)&xh, g_x_hi);
    cudaGetSymbolAddress((void**)&w2h, g_w2t_hi);
    cudaGetSymbolAddress((void**)&ewh, g_ew_hi);

    cudaFuncSetAttribute(hgemm_enc, cudaFuncAttributeMaxDynamicSharedMemorySize,
                         SMEM_TOTAL);
    cudaFuncSetAttribute(hgemm_screen, cudaFuncAttributeMaxDynamicSharedMemorySize,
                         SMEM_TOTAL);

    // Launch order puts hgemm_screen in the ncu capture slot (4th launch).
    // 1) LayerNorm -> fp16 split (+ g_key init)
    ln_kernel<<<MM, 256>>>(x, gamma, beta);

    // 2) fused codebook matrix W2^T (+ csq in d0==0 blocks)
    w2t_kernel<<<dim3(CC / 128, DD / 128), 256>>>(projw, cb);

    // 3) enc weight split
    split_hi_kernel<<<(QQ * DD + 255) / 256, 256>>>(encw, ewh, QQ * DD);

    // 4) label screen (f16-accum 1-pass): scores + per-row approx min
    dim3 gridx(CC / 128, MM / 128);
    hgemm_screen<<<gridx, 256, SMEM_TOTAL>>>(xh, w2h, DD);

    // 5) encoder GEMM (fp32-accum 1-pass)
    dim3 grid12(QQ / 128, MM / 128);
    hgemm_enc<<<grid12, 256, SMEM_TOTAL>>>(xh, ewh, DD, QQ, encb, enc_out);

    // 6) exact refinement -> labels
    refine_kernel<<<MM / 8, 256>>>(labels);

    (void)in_sizes; (void)n_in;
}

// round 11
// speedup vs baseline: 1.4397x; 1.0562x over previous
#include <cuda_runtime.h>
#include <cuda_fp16.h>
#include <math_constants.h>
#include <cstdint>

// Problem constants
#define BB 8
#define TT 8192
#define DD 512
#define QQ 1024
#define CC 4096
#define MM (BB * TT)   // 65536

typedef __half h16;

// ---------------------------------------------------------------------------
// Scratch (__device__ globals; allocation-free rule)
// ---------------------------------------------------------------------------
__device__ __align__(16) h16 g_x_hi[(size_t)MM * DD];
__device__ __align__(16) h16 g_x_lo[(size_t)MM * DD];
__device__ __align__(16) h16 g_w2t_hi[(size_t)CC * DD];   // W2^T [C][D]
__device__ __align__(16) h16 g_w2t_lo[(size_t)CC * DD];
__device__ __align__(16) h16 g_ew_hi[(size_t)QQ * DD];
__device__ __align__(16) h16 g_sc[(size_t)MM * CC];       // approx scores (512 MB)
__device__ float g_csq[CC];
__device__ unsigned long long g_key[MM];

// ---------------------------------------------------------------------------
// PTX helpers
// ---------------------------------------------------------------------------
__device__ __forceinline__ uint32_t smem_u32(const void* p) {
    uint32_t a;
    asm("{ .reg .u64 t; cvta.to.shared.u64 t, %1; cvt.u32.u64 %0, t; }"
        : "=r"(a) : "l"(p));
    return a;
}
__device__ __forceinline__ void cp16(uint32_t dst, const void* src) {
    asm volatile("cp.async.cg.shared.global [%0], [%1], 16;" :: "r"(dst), "l"(src));
}
#define CP_COMMIT() asm volatile("cp.async.commit_group;")
#define CP_WAIT1()  asm volatile("cp.async.wait_group 1;")
#define CP_WAIT0()  asm volatile("cp.async.wait_group 0;")

__device__ __forceinline__ void ldmx4(uint32_t* r, uint32_t addr) {
    asm volatile("ldmatrix.sync.aligned.m8n8.x4.shared.b16 {%0,%1,%2,%3}, [%4];"
                 : "=r"(r[0]), "=r"(r[1]), "=r"(r[2]), "=r"(r[3]) : "r"(addr));
}
__device__ __forceinline__ void mma16816_f32(float* d, const uint32_t* a,
                                             uint32_t b0, uint32_t b1) {
    asm volatile("mma.sync.aligned.m16n8k16.row.col.f32.f16.f16.f32 "
                 "{%0,%1,%2,%3}, {%4,%5,%6,%7}, {%8,%9}, {%0,%1,%2,%3};"
                 : "+f"(d[0]), "+f"(d[1]), "+f"(d[2]), "+f"(d[3])
                 : "r"(a[0]), "r"(a[1]), "r"(a[2]), "r"(a[3]), "r"(b0), "r"(b1));
}
__device__ __forceinline__ void mma16816_f16(uint32_t* d, const uint32_t* a,
                                             uint32_t b0, uint32_t b1) {
    asm volatile("mma.sync.aligned.m16n8k16.row.col.f16.f16.f16.f16 "
                 "{%0,%1}, {%2,%3,%4,%5}, {%6,%7}, {%0,%1};"
                 : "+r"(d[0]), "+r"(d[1])
                 : "r"(a[0]), "r"(a[1]), "r"(a[2]), "r"(a[3]), "r"(b0), "r"(b1));
}

// float <-> order-preserving uint32 (ascending)
__device__ __forceinline__ uint32_t ford(float s) {
    uint32_t b = __float_as_uint(s);
    return (b & 0x80000000u) ? ~b : (b | 0x80000000u);
}
__device__ __forceinline__ float unford(uint32_t f) {
    uint32_t b = (f & 0x80000000u) ? (f & 0x7FFFFFFFu) : ~f;
    return __uint_as_float(b);
}

// ---------------------------------------------------------------------------
// Shared GEMM skeleton: BM=BN=128, BK=64, 256 thr, cp.async pipeline.
// Stage size fixed (32KB); stage COUNT is a macro parameter so the screen
// kernel can trade pipeline depth for occupancy.
// ---------------------------------------------------------------------------
#define T_A    0
#define T_B    16384
#define STG1   32768
#define NSTAGE_SCREEN 2     // 64KB  -> 3 CTAs/SM
#define NSTAGE_ENC    3     // 96KB  -> 2 CTAs/SM
#define SMEM_SCREEN (NSTAGE_SCREEN * STG1)
#define SMEM_ENC    (NSTAGE_ENC * STG1)

#define GEMM_PRE()                                                            \
    extern __shared__ __align__(1024) char smem[];                            \
    const uint32_t sb = smem_u32(smem);                                       \
    const int tid  = threadIdx.x;                                             \
    const int lane = tid & 31;                                                \
    const int wid  = tid >> 5;                                                \
    const int wy   = wid >> 2;                                                \
    const int wx   = wid & 3;                                                 \
    const size_t bm = (size_t)blockIdx.y * 128;                               \
    const size_t bn = (size_t)blockIdx.x * 128;                               \
    const int lrow  = tid >> 1;                                               \
    const int lhalf = tid & 1;                                                \
    const uint32_t swr   = (uint32_t)((lrow & 7) << 4);                       \
    const uint32_t rbase = (uint32_t)(lrow * 128);                            \
    const char* pA = (const char*)(A + (bm + lrow) * (size_t)K);              \
    const char* pB = (const char*)(B + (bn + lrow) * (size_t)K);              \
    const int nch = K >> 6;                                                   \
    auto load_stage = [&](int s, int kc) {                                    \
        uint32_t st = sb + (uint32_t)s * STG1;                                \
        int kbyte0 = kc << 7;                                                 \
        _Pragma("unroll")                                                     \
        for (int i = 0; i < 4; i++) {                                         \
            uint32_t ko = (uint32_t)(lhalf * 64 + i * 16);                    \
            uint32_t d  = rbase + (ko ^ swr);                                 \
            cp16(st + T_A + d, pA + kbyte0 + ko);                             \
            cp16(st + T_B + d, pB + kbyte0 + ko);                             \
        }                                                                     \
        CP_COMMIT();                                                          \
    };                                                                        \
    const int rl  = lane & 15;                                                \
    const uint32_t kbh = (uint32_t)((lane >> 4) << 4);                        \
    uint32_t a_base[4], a_swz[4], b_base[2], b_swz[2];                        \
    _Pragma("unroll")                                                         \
    for (int mf = 0; mf < 4; mf++) {                                          \
        int r = wy * 64 + mf * 16 + rl;                                       \
        a_base[mf] = (uint32_t)(r * 128);                                     \
        a_swz[mf]  = (uint32_t)((r & 7) << 4);                                \
    }                                                                         \
    _Pragma("unroll")                                                         \
    for (int np = 0; np < 2; np++) {                                          \
        int n = wx * 32 + np * 16 + rl;                                       \
        b_base[np] = (uint32_t)(n * 128);                                     \
        b_swz[np]  = (uint32_t)((n & 7) << 4);                                \
    }

// NST-stage pipelined main loop, one barrier per chunk.
#define GEMM_MAINLOOP(NST)                                                    \
    load_stage(0, 0);                                                         \
    if ((NST) > 2 && nch > 1) load_stage(1, 1);                               \
    int sidx = 0;                                                             \
    for (int kc = 0; kc < nch; kc++) {                                        \
        if ((NST) == 2) {                                                     \
            if (kc + 1 < nch) load_stage((kc + 1) & 1, kc + 1);               \
            if (kc + 1 < nch) { CP_WAIT1(); } else { CP_WAIT0(); }            \
            __syncthreads();                                                  \
            compute_stage(kc & 1);                                            \
            __syncthreads();                                                  \
        } else {                                                              \
            if (kc + 1 < nch) { CP_WAIT1(); } else { CP_WAIT0(); }            \
            __syncthreads();                                                  \
            if (kc + 2 < nch) {                                               \
                int s2 = sidx + 2; if (s2 >= (NST)) s2 -= (NST);              \
                load_stage(s2, kc + 2);                                       \
            }                                                                 \
            compute_stage(sidx);                                              \
            if (++sidx == (NST)) sidx = 0;                                    \
        }                                                                     \
    }

// ---------------------------------------------------------------------------
// Screen GEMM: f16 accum, 1-pass hi, NSTAGE=2 + 3 CTAs/SM for latency hiding.
// score = csq[c] - 2*dot; direct fp16 score store + per-row packed atomicMin.
// ---------------------------------------------------------------------------
__global__ __launch_bounds__(256, 3) void hgemm_screen(
    const h16* __restrict__ A, const h16* __restrict__ B, int K)
{
    GEMM_PRE();

    uint32_t acc[4][4][2];   // half2 pairs: [sub] -> rows r, r+8; cols c,c+1
    #pragma unroll
    for (int i = 0; i < 4; i++)
        #pragma unroll
        for (int j = 0; j < 4; j++) { acc[i][j][0] = 0u; acc[i][j][1] = 0u; }

    auto compute_stage = [&](int s) {
        uint32_t base = sb + (uint32_t)s * STG1;
        uint32_t aP = base + T_A, bP = base + T_B;
        #pragma unroll
        for (int ks = 0; ks < 4; ks++) {
            uint32_t kb = (uint32_t)(ks * 32) + kbh;
            uint32_t a_h[4][4], b_h[2][4];
            #pragma unroll
            for (int mf = 0; mf < 4; mf++)
                ldmx4(a_h[mf], aP + a_base[mf] + (kb ^ a_swz[mf]));
            #pragma unroll
            for (int np = 0; np < 2; np++)
                ldmx4(b_h[np], bP + b_base[np] + (kb ^ b_swz[np]));
            #pragma unroll
            for (int mf = 0; mf < 4; mf++)
                #pragma unroll
                for (int nf = 0; nf < 4; nf++) {
                    int p = nf >> 1, q = nf & 1;
                    mma16816_f16(acc[mf][nf], a_h[mf], b_h[p][q], b_h[p][q + 2]);
                }
        }
    };

    GEMM_MAINLOOP(NSTAGE_SCREEN);

    const int qrow = lane >> 2;
    const int c2   = 2 * (lane & 3);
    #pragma unroll
    for (int mf = 0; mf < 4; mf++) {
        #pragma unroll
        for (int sub = 0; sub < 2; sub++) {
            size_t row = bm + (size_t)(wy * 64 + mf * 16 + sub * 8 + qrow);
            unsigned long long best = 0xFFFFFFFFFFFFFFFFull;
            #pragma unroll
            for (int nf = 0; nf < 4; nf++) {
                int col = (int)bn + wx * 32 + nf * 8 + c2;
                __half2 d2 = *(__half2*)&acc[mf][nf][sub];
                float s0 = g_csq[col]     - 2.0f * __half2float(__low2half(d2));
                float s1 = g_csq[col + 1] - 2.0f * __half2float(__high2half(d2));
                __half2 hp = __floats2half2_rn(s0, s1);
                uint32_t u; *(__half2*)&u = hp;
                __stcs((uint32_t*)(g_sc + row * CC + col), u);
                unsigned long long k0 =
                    ((unsigned long long)ford(s0) << 32) | (uint32_t)col;
                unsigned long long k1 =
                    ((unsigned long long)ford(s1) << 32) | (uint32_t)(col + 1);
                if (k0 < best) best = k0;
                if (k1 < best) best = k1;
            }
            unsigned long long o;
            o = __shfl_down_sync(0xFFFFFFFFu, best, 2);
            if (o < best) best = o;
            o = __shfl_down_sync(0xFFFFFFFFu, best, 1);
            if (o < best) best = o;
            if ((lane & 3) == 0) atomicMin(&g_key[row], best);
        }
    }
}

// ---------------------------------------------------------------------------
// Encoder GEMM: fp32 accum, 1-pass hi, NSTAGE=3 (unchanged).
// ---------------------------------------------------------------------------
__global__ __launch_bounds__(256, 2) void hgemm_enc(
    const h16* __restrict__ A, const h16* __restrict__ B,
    int K, int Ntot, const float* __restrict__ bias, float* __restrict__ outf)
{
    GEMM_PRE();

    float acc[4][4][4];
    #pragma unroll
    for (int i = 0; i < 4; i++)
        #pragma unroll
        for (int j = 0; j < 4; j++)
            #pragma unroll
            for (int k = 0; k < 4; k++) acc[i][j][k] = 0.f;

    auto compute_stage = [&](int s) {
        uint32_t base = sb + (uint32_t)s * STG1;
        uint32_t aP = base + T_A, bP = base + T_B;
        #pragma unroll
        for (int ks = 0; ks < 4; ks++) {
            uint32_t kb = (uint32_t)(ks * 32) + kbh;
            uint32_t a_h[4][4], b_h[2][4];
            #pragma unroll
            for (int mf = 0; mf < 4; mf++)
                ldmx4(a_h[mf], aP + a_base[mf] + (kb ^ a_swz[mf]));
            #pragma unroll
            for (int np = 0; np < 2; np++)
                ldmx4(b_h[np], bP + b_base[np] + (kb ^ b_swz[np]));
            #pragma unroll
            for (int mf = 0; mf < 4; mf++)
                #pragma unroll
                for (int nf = 0; nf < 4; nf++) {
                    int p = nf >> 1, q = nf & 1;
                    mma16816_f32(acc[mf][nf], a_h[mf], b_h[p][q], b_h[p][q + 2]);
                }
        }
    };

    GEMM_MAINLOOP(NSTAGE_ENC);

    const int qrow = lane >> 2;
    const int c2   = 2 * (lane & 3);
    #pragma unroll
    for (int mf = 0; mf < 4; mf++) {
        size_t r0 = bm + (size_t)(wy * 64 + mf * 16 + qrow);
        #pragma unroll
        for (int nf = 0; nf < 4; nf++) {
            size_t col = bn + (size_t)(wx * 32 + nf * 8 + c2);
            float b0 = bias[col], b1 = bias[col + 1];
            #pragma unroll
            for (int sub = 0; sub < 2; sub++) {
                size_t r = r0 + sub * 8;
                float2 o;
                o.x = acc[mf][nf][sub * 2 + 0] + b0;
                o.y = acc[mf][nf][sub * 2 + 1] + b1;
                *(float2*)(outf + r * Ntot + col) = o;
            }
        }
    }
}

// ---------------------------------------------------------------------------
// Refine (R7-proven): streaming uint4 scan; candidates within MARGIN of the
// screen's approx min; exact fp32 recompute; low-index tie break.
// ---------------------------------------------------------------------------
#define MARGIN 8.0f

__global__ __launch_bounds__(256) void refine_kernel(float* __restrict__ labels) {
    int warp = blockIdx.x * 8 + (threadIdx.x >> 5);
    int lane = threadIdx.x & 31;
    size_t row = (size_t)warp;

    float amin   = unford((uint32_t)(g_key[row] >> 32));
    float thresh = amin + MARGIN;
    __half hthr  = __float2half_ru(thresh);

    const h16* sr = g_sc + row * CC;
    float best = CUDART_INF_F;
    int bestc = 0;

    for (int base = 0; base < CC; base += 256) {
        uint4 v = *(const uint4*)(sr + base + lane * 8);
        __half2 p[4];
        p[0] = *(__half2*)&v.x; p[1] = *(__half2*)&v.y;
        p[2] = *(__half2*)&v.z; p[3] = *(__half2*)&v.w;
        __half2 mn2 = __hmin2(__hmin2(p[0], p[1]), __hmin2(p[2], p[3]));
        __half mn = __hmin(__low2half(mn2), __high2half(mn2));
        uint32_t mask = __ballot_sync(0xFFFFFFFFu, __hle(mn, hthr));
        while (mask) {
            int bit = __ffs(mask) - 1;
            mask &= mask - 1;
            #pragma unroll
            for (int j = 0; j < 8; j++) {
                float sv = __half2float(__shfl_sync(0xFFFFFFFFu,
                             ((const __half*)p)[j], bit));
                if (sv > thresh) continue;
                int c = base + bit * 8 + j;
                const h16* xh = g_x_hi + row * DD;
                const h16* xl = g_x_lo + row * DD;
                const h16* wh = g_w2t_hi + (size_t)c * DD;
                const h16* wl = g_w2t_lo + (size_t)c * DD;
                float dot = 0.f;
                #pragma unroll
                for (int jj = 0; jj < 16; jj++) {
                    int d = lane + 32 * jj;
                    float a = __half2float(xh[d]) + __half2float(xl[d]);
                    float b = __half2float(wh[d]) + __half2float(wl[d]);
                    dot = fmaf(a, b, dot);
                }
                #pragma unroll
                for (int off = 16; off > 0; off >>= 1)
                    dot += __shfl_down_sync(0xFFFFFFFFu, dot, off);
                if (lane == 0) {
                    float sc = g_csq[c] - 2.0f * dot;
                    if (sc < best || (sc == best && c < bestc)) { best = sc; bestc = c; }
                }
            }
        }
    }
    if (lane == 0) labels[row] = (float)bestc;
}

// ---------------------------------------------------------------------------
// W2^T precompute + fused csq.
// ---------------------------------------------------------------------------
__global__ __launch_bounds__(256) void w2t_kernel(const float* __restrict__ projw,
                                                  const float* __restrict__ cb) {
    __shared__ __align__(16) float As[8][128];
    __shared__ __align__(16) float Bs[8][128];
    __shared__ float cred[2][128];

    int tid = threadIdx.x;
    int c0 = blockIdx.x * 128;
    int d0 = blockIdx.y * 128;
    int lr = tid >> 5, lc = (tid & 31) * 4;
    int ty = tid >> 4, tx = tid & 15;

    int qcol = tid & 127;
    int qgrp = tid >> 7;
    float csum = 0.f;

    float acc[8][8];
    #pragma unroll
    for (int i = 0; i < 8; i++)
        #pragma unroll
        for (int j = 0; j < 8; j++) acc[i][j] = 0.f;

    for (int k0 = 0; k0 < QQ; k0 += 8) {
        *(float4*)&As[lr][lc] = *(const float4*)(cb + (size_t)(k0 + lr) * CC + c0 + lc);
        *(float4*)&Bs[lr][lc] = *(const float4*)(projw + (size_t)(k0 + lr) * DD + d0 + lc);
        __syncthreads();

        if (d0 == 0) {
            #pragma unroll
            for (int r = 0; r < 4; r++) {
                float v = As[qgrp * 4 + r][qcol];
                csum = fmaf(v, v, csum);
            }
        }

        #pragma unroll
        for (int k = 0; k < 8; k++) {
            float ar[8], br[8];
            float4 a0 = *(const float4*)&As[k][ty * 8];
            float4 a1 = *(const float4*)&As[k][ty * 8 + 4];
            float4 b0 = *(const float4*)&Bs[k][tx * 8];
            float4 b1 = *(const float4*)&Bs[k][tx * 8 + 4];
            ar[0]=a0.x; ar[1]=a0.y; ar[2]=a0.z; ar[3]=a0.w;
            ar[4]=a1.x; ar[5]=a1.y; ar[6]=a1.z; ar[7]=a1.w;
            br[0]=b0.x; br[1]=b0.y; br[2]=b0.z; br[3]=b0.w;
            br[4]=b1.x; br[5]=b1.y; br[6]=b1.z; br[7]=b1.w;
            #pragma unroll
            for (int i = 0; i < 8; i++)
                #pragma unroll
                for (int j = 0; j < 8; j++)
                    acc[i][j] = fmaf(ar[i], br[j], acc[i][j]);
        }
        __syncthreads();
    }

    if (d0 == 0) {
        cred[qgrp][qcol] = csum;
        __syncthreads();
        if (tid < 128) g_csq[c0 + tid] = cred[0][tid] + cred[1][tid];
    }

    #pragma unroll
    for (int i = 0; i < 8; i++) {
        size_t rowo = (size_t)(c0 + ty * 8 + i) * DD + d0 + tx * 8;
        #pragma unroll
        for (int j = 0; j < 8; j++) {
            float v = acc[i][j];
            h16 h = __float2half(v);
            g_w2t_hi[rowo + j] = h;
            g_w2t_lo[rowo + j] = __float2half(v - __half2float(h));
        }
    }
}

// ---------------------------------------------------------------------------
// LayerNorm over D=512, writes fp16 hi/lo split + inits g_key for its row.
// ---------------------------------------------------------------------------
__global__ __launch_bounds__(256) void ln_kernel(const float* __restrict__ x,
                                                 const float* __restrict__ gamma,
                                                 const float* __restrict__ beta) {
    int r = blockIdx.x;
    const float* xr = x + (size_t)r * DD;
    int t = threadIdx.x;

    if (t == 0) g_key[r] = 0xFFFFFFFFFFFFFFFFull;

    float v0 = xr[t], v1 = xr[t + 256];
    float s = v0 + v1, ss = v0 * v0 + v1 * v1;
    #pragma unroll
    for (int off = 16; off > 0; off >>= 1) {
        s  += __shfl_down_sync(0xFFFFFFFFu, s,  off);
        ss += __shfl_down_sync(0xFFFFFFFFu, ss, off);
    }
    __shared__ float sh_s[8], sh_ss[8];
    int w = t >> 5, l = t & 31;
    if (l == 0) { sh_s[w] = s; sh_ss[w] = ss; }
    __syncthreads();
    if (t == 0) {
        float S = 0.f, SS = 0.f;
        #pragma unroll
        for (int i = 0; i < 8; i++) { S += sh_s[i]; SS += sh_ss[i]; }
        sh_s[0]  = S * (1.0f / DD);
        sh_ss[0] = SS * (1.0f / DD);
    }
    __syncthreads();
    float mu = sh_s[0];
    float rs = rsqrtf(sh_ss[0] - mu * mu + 1e-5f);

    float y0 = (v0 - mu) * rs * gamma[t]       + beta[t];
    float y1 = (v1 - mu) * rs * gamma[t + 256] + beta[t + 256];

    size_t base = (size_t)r * DD;
    h16 h0 = __float2half(y0), h1 = __float2half(y1);
    g_x_hi[base + t]       = h0;
    g_x_hi[base + t + 256] = h1;
    g_x_lo[base + t]       = __float2half(y0 - __half2float(h0));
    g_x_lo[base + t + 256] = __float2half(y1 - __half2float(h1));
}

// ---------------------------------------------------------------------------
__global__ __launch_bounds__(256) void split_hi_kernel(const float* __restrict__ src,
                                                       h16* __restrict__ hi, int n) {
    int i = blockIdx.x * 256 + threadIdx.x;
    if (i < n) hi[i] = __float2half(src[i]);
}

// ---------------------------------------------------------------------------
extern "C" void kernel_launch(void* const* d_in, const int* in_sizes, int n_in,
                              void* d_out, int out_size) {
    const float* x     = (const float*)d_in[0];
    const float* gamma = (const float*)d_in[1];
    const float* beta  = (const float*)d_in[2];
    const float* projw = (const float*)d_in[3];
    const float* cb    = (const float*)d_in[4];
    const float* encw  = (const float*)d_in[5];
    const float* encb  = (const float*)d_in[6];

    float* out     = (float*)d_out;
    float* enc_out = out;                               // (M, Q) fp32
    float* labels  = out + ((size_t)out_size - MM);     // (M,) as fp32

    h16 *xh, *w2h, *ewh;
    cudaGetSymbolAddress((void**)&xh, g_x_hi);
    cudaGetSymbolAddress((void**)&w2h, g_w2t_hi);
    cudaGetSymbolAddress((void**)&ewh, g_ew_hi);

    cudaFuncSetAttribute(hgemm_enc, cudaFuncAttributeMaxDynamicSharedMemorySize,
                         SMEM_ENC);
    cudaFuncSetAttribute(hgemm_screen, cudaFuncAttributeMaxDynamicSharedMemorySize,
                         SMEM_SCREEN);

    // Launch order keeps hgemm_screen in the ncu capture slot (4th launch).
    // 1) LayerNorm -> fp16 split (+ g_key init)
    ln_kernel<<<MM, 256>>>(x, gamma, beta);

    // 2) fused codebook matrix W2^T (+ csq in d0==0 blocks)
    w2t_kernel<<<dim3(CC / 128, DD / 128), 256>>>(projw, cb);

    // 3) enc weight split
    split_hi_kernel<<<(QQ * DD + 255) / 256, 256>>>(encw, ewh, QQ * DD);

    // 4) label screen (f16-accum 1-pass, 2-stage, 3 CTAs/SM)
    dim3 gridx(CC / 128, MM / 128);
    hgemm_screen<<<gridx, 256, SMEM_SCREEN>>>(xh, w2h, DD);

    // 5) encoder GEMM (fp32-accum 1-pass, 3-stage)
    dim3 grid12(QQ / 128, MM / 128);
    hgemm_enc<<<grid12, 256, SMEM_ENC>>>(xh, ewh, DD, QQ, encb, enc_out);

    // 6) exact refinement -> labels
    refine_kernel<<<MM / 8, 256>>>(labels);

    (void)in_sizes; (void)n_in;
}